// round 3
// baseline (speedup 1.0000x reference)
#include <cuda_runtime.h>
#include <math.h>

#define T_STEPS 2048
#define BATCH   64
#define IN_DIM  27
#define H1      400
#define H2      200
#define GRID_R  100          // CTAs in recurrence kernel (4 hidden units each)
#define UPC     4            // hidden units per CTA
#define K4      (H1 / 4)     // 100 k-quads

// ---------------- device scratch (static; zero-init) ----------------
// g_xw[t][row(1600)][b]  : x@W_ih^T + b_ih + b_hh
static __device__ float g_xw[(size_t)T_STEPS * 4 * H1 * BATCH];
// g_hr : interleaved [t][k>>2][b][k&3]; slot t=0 is h_{-1}=0 (never written)
static __device__ float g_hr[(size_t)(T_STEPS + 1) * H1 * BATCH];
static __device__ unsigned int g_bar;

__device__ __forceinline__ void ffma2(unsigned long long &acc,
                                      unsigned long long a, unsigned long long b) {
    asm("fma.rn.f32x2 %0, %1, %2, %0;" : "+l"(acc) : "l"(a), "l"(b));
}

// =====================================================================
// Kernel 1: xw[t][r][b] = word[t,b,:] . W_ih[r,:] + b_ih[r] + b_hh[r]
// grid (25, 2048), block 256. Also resets the grid-barrier counter.
// =====================================================================
__global__ void __launch_bounds__(256) k_xw(const float* __restrict__ word,
                                            const float* __restrict__ Wih,
                                            const float* __restrict__ bih,
                                            const float* __restrict__ bhh) {
    __shared__ float xs[IN_DIM * 68];   // [i][b] padded stride 68
    __shared__ float ws[64 * 28];       // [r][i] padded
    __shared__ float bs[64];
    const int t = blockIdx.y;
    const int rbase = blockIdx.x * 64;
    const int tid = threadIdx.x;

    if (blockIdx.x == 0 && blockIdx.y == 0 && tid == 0) g_bar = 0u;

    for (int j = tid; j < BATCH * IN_DIM; j += 256) {     // smem transpose of word[t]
        int b = j / IN_DIM, i = j - b * IN_DIM;
        xs[i * 68 + b] = word[(size_t)t * (BATCH * IN_DIM) + j];
    }
    for (int j = tid; j < 64 * IN_DIM; j += 256) {
        int r = j / IN_DIM, i = j - r * IN_DIM;
        ws[r * 28 + i] = Wih[(size_t)(rbase + r) * IN_DIM + i];
    }
    if (tid < 64) bs[tid] = bih[rbase + tid] + bhh[rbase + tid];
    __syncthreads();

    const int rq = tid >> 4;            // 4 rows per thread
    const int bq = (tid & 15) * 4;      // 4 batches per thread
    float acc[4][4];
    #pragma unroll
    for (int r = 0; r < 4; r++) {
        float bv = bs[rq * 4 + r];
        #pragma unroll
        for (int b = 0; b < 4; b++) acc[r][b] = bv;
    }
    #pragma unroll 3
    for (int i = 0; i < IN_DIM; i++) {
        float4 xv = *(const float4*)&xs[i * 68 + bq];
        #pragma unroll
        for (int r = 0; r < 4; r++) {
            float w = ws[(rq * 4 + r) * 28 + i];
            acc[r][0] += w * xv.x; acc[r][1] += w * xv.y;
            acc[r][2] += w * xv.z; acc[r][3] += w * xv.w;
        }
    }
    size_t base = ((size_t)t * (4 * H1) + rbase) * BATCH;
    #pragma unroll
    for (int r = 0; r < 4; r++) {
        float4 v = make_float4(acc[r][0], acc[r][1], acc[r][2], acc[r][3]);
        *(float4*)&g_xw[base + (size_t)(rq * 4 + r) * BATCH + bq] = v;
    }
}

// =====================================================================
// Kernel 2: persistent recurrence. grid GRID_R, block 256, 1 CTA/SM.
// smem: hs[k4][b][4] (25600f) | ws[16 rows][400 k] (6400f) | gb[16][64] (1024f)
// =====================================================================
#define HS_F 25600
#define WS_F 6400
#define GB_F 1024
#define REC_SMEM_B ((HS_F + WS_F + GB_F) * 4)

__global__ void __launch_bounds__(256, 1) k_rec(const float* __restrict__ Whh) {
    extern __shared__ float sm[];
    float* hs = sm;                    // interleaved h
    float* ws = sm + HS_F;             // [lr][k]
    float* gb = sm + HS_F + WS_F;      // [lr][b]

    const int tid   = threadIdx.x;
    const int lane  = tid & 31;
    const int warp  = tid >> 5;
    const int kbase = blockIdx.x * UPC;

    // ---- stage W_hh slice once: ws[lr][k], lr=g*4+q -> global row g*H1+kbase+q
    for (int idx = tid; idx < 16 * H1; idx += 256) {
        int lr = idx / H1, k = idx - lr * H1;
        int g = lr >> 2, q = lr & 3;
        ws[lr * H1 + k] = Whh[(size_t)(g * H1 + kbase + q) * H1 + k];
    }

    // dot mapping: warp -> (row group rg = warp>>1, batch half = warp&1)
    const int b  = (warp & 1) * 32 + lane;     // batch 0..63
    const int rg = warp >> 1;                  // row group 0..3 (rows rg*4..rg*4+3)

    // combine mapping: cq = unit 0..3, cb = batch 0..63 (coalesced hr store)
    const int cq = tid & 3, cb = tid >> 2;
    float c_val = 0.0f;

    __syncthreads();

    for (int t = 0; t < T_STEPS; t++) {
        // ---- init accumulators from precomputed xw (low half; high half = 0)
        unsigned long long acc[4];
        {
            const float* xwp = g_xw + (size_t)t * (4 * H1) * BATCH;
            #pragma unroll
            for (int r = 0; r < 4; r++) {
                int lr = rg * 4 + r;
                int grow = (lr >> 2) * H1 + kbase + (lr & 3);
                float xv = __ldg(&xwp[(size_t)grow * BATCH + b]);
                acc[r] = (unsigned long long)__float_as_uint(xv);
            }
        }

        // ---- stage h_r[t] into smem (linear copy; layout already interleaved)
        {
            const float4* hsrc = (const float4*)(g_hr + (size_t)t * (H1 * BATCH));
            float4* hdst = (float4*)hs;
            #pragma unroll
            for (int i = tid; i < (H1 * BATCH) / 4; i += 256)
                hdst[i] = hsrc[i];
        }
        __syncthreads();

        // ---- dots: acc[r] (+=) over k, f32x2 packed over (even k, odd k)
        {
            const ulonglong2* hrow = (const ulonglong2*)hs;   // [k4*64 + b]
            #pragma unroll 4
            for (int k4 = 0; k4 < K4; k4++) {
                ulonglong2 h4 = hrow[k4 * 64 + b];
                #pragma unroll
                for (int r = 0; r < 4; r++) {
                    ulonglong2 w4 = *(const ulonglong2*)&ws[(rg * 4 + r) * H1 + k4 * 4];
                    ffma2(acc[r], h4.x, w4.x);
                    ffma2(acc[r], h4.y, w4.y);
                }
            }
            #pragma unroll
            for (int r = 0; r < 4; r++) {
                float lo = __uint_as_float((unsigned)acc[r]);
                float hi = __uint_as_float((unsigned)(acc[r] >> 32));
                gb[(rg * 4 + r) * BATCH + b] = lo + hi;
            }
        }
        __syncthreads();

        // ---- combine: LSTM cell for (unit cq, batch cb)
        {
            float xi = gb[(0 * 4 + cq) * BATCH + cb];
            float xf = gb[(1 * 4 + cq) * BATCH + cb];
            float xg = gb[(2 * 4 + cq) * BATCH + cb];
            float xo = gb[(3 * 4 + cq) * BATCH + cb];
            float iv = 1.0f / (1.0f + expf(-xi));
            float fv = 1.0f / (1.0f + expf(-xf));
            float ov = 1.0f / (1.0f + expf(-xo));
            float gv = tanhf(xg);
            float cn = fv * c_val + iv * gv;
            float hn = ov * tanhf(cn);
            c_val = fmaxf(cn, 0.0f);
            float hr = fmaxf(hn, 0.0f);
            // interleaved store: [t+1][k4=blockIdx.x][b=cb][j=cq]  (fully coalesced)
            g_hr[(size_t)(t + 1) * (H1 * BATCH) +
                 (size_t)blockIdx.x * (UPC * BATCH) + cb * 4 + cq] = hr;
        }

        // ---- grid barrier (CG-style: fence all, arrive tid0, acquire-poll, sync)
        __threadfence();
        __syncthreads();
        if (tid == 0) {
            atomicAdd(&g_bar, 1u);
            unsigned target = (unsigned)(t + 1) * GRID_R;
            unsigned v;
            do {
                asm volatile("ld.acquire.gpu.u32 %0, [%1];" : "=r"(v) : "l"(&g_bar));
            } while (v < target);
        }
        __syncthreads();
    }
}

// =====================================================================
// Kernel 3: MLP head per timestep. grid 2048, block 256.
// smem: hs (interleaved, 25600f) | hid[j][b] (12800f)
// =====================================================================
#define HEAD_SMEM_B ((HS_F + H2 * BATCH) * 4)

__global__ void __launch_bounds__(256) k_head(const float* __restrict__ Wfc,
                                              const float* __restrict__ bfc,
                                              const float* __restrict__ Wout,
                                              const float* __restrict__ bout,
                                              float* __restrict__ out) {
    extern __shared__ float sm[];
    float* hs  = sm;
    float* hid = sm + HS_F;
    const int t = blockIdx.x;
    const int tid = threadIdx.x;

    const float4* hsrc = (const float4*)(g_hr + (size_t)(t + 1) * (H1 * BATCH));
    for (int i = tid; i < (H1 * BATCH) / 4; i += 256)
        ((float4*)hs)[i] = hsrc[i];
    __syncthreads();

    const int jrow = tid >> 4;
    const int bq   = (tid & 15) * 4;
    for (int j = jrow; j < H2; j += 16) {
        float bv = bfc[j];
        float4 acc = make_float4(bv, bv, bv, bv);
        const float4* wr = (const float4*)(Wfc + (size_t)j * H1);
        #pragma unroll 4
        for (int k4 = 0; k4 < K4; k4++) {
            float4 w4 = wr[k4];
            float4 h0 = *(const float4*)&hs[k4 * 256 + (bq + 0) * 4];
            float4 h1 = *(const float4*)&hs[k4 * 256 + (bq + 1) * 4];
            float4 h2 = *(const float4*)&hs[k4 * 256 + (bq + 2) * 4];
            float4 h3 = *(const float4*)&hs[k4 * 256 + (bq + 3) * 4];
            acc.x += w4.x * h0.x + w4.y * h0.y + w4.z * h0.z + w4.w * h0.w;
            acc.y += w4.x * h1.x + w4.y * h1.y + w4.z * h1.z + w4.w * h1.w;
            acc.z += w4.x * h2.x + w4.y * h2.y + w4.z * h2.z + w4.w * h2.w;
            acc.w += w4.x * h3.x + w4.y * h3.y + w4.z * h3.z + w4.w * h3.w;
        }
        acc.x = fmaxf(acc.x, 0.f); acc.y = fmaxf(acc.y, 0.f);
        acc.z = fmaxf(acc.z, 0.f); acc.w = fmaxf(acc.w, 0.f);
        *(float4*)&hid[j * BATCH + bq] = acc;
    }
    __syncthreads();

    if (tid < BATCH) {
        float s = bout[0];
        #pragma unroll 8
        for (int j = 0; j < H2; j++)
            s += hid[j * BATCH + tid] * Wout[j];
        out[(size_t)t * BATCH + tid] = 1.0f / (1.0f + expf(-s));
    }
}

// =====================================================================
extern "C" void kernel_launch(void* const* d_in, const int* in_sizes, int n_in,
                              void* d_out, int out_size) {
    const float* word = (const float*)d_in[0];
    const float* Wih  = (const float*)d_in[1];
    const float* Whh  = (const float*)d_in[2];
    const float* bih  = (const float*)d_in[3];
    const float* bhh  = (const float*)d_in[4];
    const float* Wfc  = (const float*)d_in[5];
    const float* bfc  = (const float*)d_in[6];
    const float* Wout = (const float*)d_in[7];
    const float* bout = (const float*)d_in[8];
    float* out = (float*)d_out;

    cudaFuncSetAttribute(k_rec,  cudaFuncAttributeMaxDynamicSharedMemorySize, REC_SMEM_B);
    cudaFuncSetAttribute(k_head, cudaFuncAttributeMaxDynamicSharedMemorySize, HEAD_SMEM_B);

    k_xw<<<dim3(25, T_STEPS), 256>>>(word, Wih, bih, bhh);
    k_rec<<<GRID_R, 256, REC_SMEM_B>>>(Whh);
    k_head<<<T_STEPS, 256, HEAD_SMEM_B>>>(Wfc, bfc, Wout, bout, out);
}

// round 4
// speedup vs baseline: 1.3458x; 1.3458x over previous
#include <cuda_runtime.h>
#include <math.h>

#define T_STEPS 2048
#define BATCH   64
#define IN_DIM  27
#define H1      400
#define H2      200
#define GRID_R  148          // recurrence CTAs: 104 x 3 units + 44 x 2 units = 400
#define K4      (H1 / 4)

// ---------------- device scratch (static; zero-init) ----------------
// g_xw[t][row(1600)][b]  : x@W_ih^T + b_ih + b_hh
static __device__ float g_xw[(size_t)T_STEPS * 4 * H1 * BATCH];
// g_hr : interleaved [t][k>>2][b][k&3]; slot t=0 is h_{-1}=0 (never written)
static __device__ float g_hr[(size_t)(T_STEPS + 1) * H1 * BATCH];
static __device__ unsigned int g_bar;

__device__ __forceinline__ void ffma2(unsigned long long &acc,
                                      unsigned long long a, unsigned long long b) {
    asm("fma.rn.f32x2 %0, %1, %2, %0;" : "+l"(acc) : "l"(a), "l"(b));
}
__device__ __forceinline__ float lo32(unsigned long long v) { return __uint_as_float((unsigned)v); }
__device__ __forceinline__ float hi32(unsigned long long v) { return __uint_as_float((unsigned)(v >> 32)); }

// =====================================================================
// Kernel 1: xw[t][r][b] = word[t,b,:] . W_ih[r,:] + b_ih[r] + b_hh[r]
// grid (25, 2048), block 256. Also resets the grid-barrier counter.
// =====================================================================
__global__ void __launch_bounds__(256) k_xw(const float* __restrict__ word,
                                            const float* __restrict__ Wih,
                                            const float* __restrict__ bih,
                                            const float* __restrict__ bhh) {
    __shared__ float xs[IN_DIM * 68];
    __shared__ float ws[64 * 28];
    __shared__ float bs[64];
    const int t = blockIdx.y;
    const int rbase = blockIdx.x * 64;
    const int tid = threadIdx.x;

    if (blockIdx.x == 0 && blockIdx.y == 0 && tid == 0) g_bar = 0u;

    for (int j = tid; j < BATCH * IN_DIM; j += 256) {
        int b = j / IN_DIM, i = j - b * IN_DIM;
        xs[i * 68 + b] = word[(size_t)t * (BATCH * IN_DIM) + j];
    }
    for (int j = tid; j < 64 * IN_DIM; j += 256) {
        int r = j / IN_DIM, i = j - r * IN_DIM;
        ws[r * 28 + i] = Wih[(size_t)(rbase + r) * IN_DIM + i];
    }
    if (tid < 64) bs[tid] = bih[rbase + tid] + bhh[rbase + tid];
    __syncthreads();

    const int rq = tid >> 4;
    const int bq = (tid & 15) * 4;
    float acc[4][4];
    #pragma unroll
    for (int r = 0; r < 4; r++) {
        float bv = bs[rq * 4 + r];
        #pragma unroll
        for (int b = 0; b < 4; b++) acc[r][b] = bv;
    }
    #pragma unroll 3
    for (int i = 0; i < IN_DIM; i++) {
        float4 xv = *(const float4*)&xs[i * 68 + bq];
        #pragma unroll
        for (int r = 0; r < 4; r++) {
            float w = ws[(rq * 4 + r) * 28 + i];
            acc[r][0] += w * xv.x; acc[r][1] += w * xv.y;
            acc[r][2] += w * xv.z; acc[r][3] += w * xv.w;
        }
    }
    size_t base = ((size_t)t * (4 * H1) + rbase) * BATCH;
    #pragma unroll
    for (int r = 0; r < 4; r++) {
        float4 v = make_float4(acc[r][0], acc[r][1], acc[r][2], acc[r][3]);
        *(float4*)&g_xw[base + (size_t)(rq * 4 + r) * BATCH + bq] = v;
    }
}

// =====================================================================
// Kernel 2: persistent recurrence. grid 148, block 256, 1 CTA/SM.
// Warps: 2 batch-groups x 4 k-splits. Each thread: 1 batch, 100 k, all rows.
// h read directly from L2 (__ldcg) — no smem staging phase.
// smem: ws[R(<=12)][400] + pr[4 ks][R][64]
// =====================================================================
template<int NU>
__device__ __forceinline__ void rec_body(const float* __restrict__ Whh,
                                         int u0, float* ws, float* pr) {
    const int R = 4 * NU;                    // gate rows this CTA
    const int tid  = threadIdx.x;
    const int lane = tid & 31;
    const int wid  = tid >> 5;
    const int ks   = wid & 3;                // k-split 0..3 (100 k each)
    const int bg   = wid >> 2;               // batch group 0..1
    const int b    = bg * 32 + lane;         // batch 0..63

    // stage W_hh slice: ws[lr][k], lr = g*NU + q  (gate-major)
    for (int idx = tid; idx < R * H1; idx += 256) {
        int lr = idx / H1, k = idx - lr * H1;
        int g = lr / NU, q = lr - g * NU;
        ws[lr * H1 + k] = Whh[(size_t)(g * H1 + u0 + q) * H1 + k];
    }

    // combine mapping: unit q (0..NU-1), batch cb
    const int cb = tid & 63;
    const int q  = tid >> 6;
    const int uu = u0 + (q < NU ? q : NU - 1);
    const size_t hr_off = (size_t)(uu >> 2) * 256 + cb * 4 + (uu & 3);
    float c_val = 0.0f;

    __syncthreads();

    const int k4lo = ks * 25;

    for (int t = 0; t < T_STEPS; t++) {
        // ---- prefetch xw for combine (latency hidden under dots) ----
        float xw0 = 0.f, xw1 = 0.f, xw2 = 0.f, xw3 = 0.f;
        if (q < NU) {
            const float* xp = g_xw + (size_t)t * (4 * H1) * BATCH;
            xw0 = __ldcg(&xp[(size_t)(0 * H1 + uu) * BATCH + cb]);
            xw1 = __ldcg(&xp[(size_t)(1 * H1 + uu) * BATCH + cb]);
            xw2 = __ldcg(&xp[(size_t)(2 * H1 + uu) * BATCH + cb]);
            xw3 = __ldcg(&xp[(size_t)(3 * H1 + uu) * BATCH + cb]);
        }

        // ---- dots: acc[lr] over thread's k-range, f32x2 packed over k ----
        unsigned long long acc[R];
        #pragma unroll
        for (int lr = 0; lr < R; lr++) acc[lr] = 0ull;

        const float* hbase = g_hr + (size_t)t * (H1 * BATCH);
        #pragma unroll 5
        for (int i = 0; i < 25; i++) {
            int k4 = k4lo + i;
            ulonglong2 h4 = __ldcg((const ulonglong2*)(hbase + k4 * 256 + b * 4));
            #pragma unroll
            for (int lr = 0; lr < R; lr++) {
                ulonglong2 w2 = *(const ulonglong2*)&ws[lr * H1 + k4 * 4];
                ffma2(acc[lr], h4.x, w2.x);
                ffma2(acc[lr], h4.y, w2.y);
            }
        }
        #pragma unroll
        for (int lr = 0; lr < R; lr++)
            pr[(ks * R + lr) * 64 + b] = lo32(acc[lr]) + hi32(acc[lr]);
        __syncthreads();

        // ---- combine: LSTM cell for (unit uu, batch cb) ----
        if (q < NU) {
            float g0 = xw0, g1 = xw1, g2 = xw2, g3 = xw3;
            #pragma unroll
            for (int s = 0; s < 4; s++) {
                g0 += pr[(s * R + 0 * NU + q) * 64 + cb];
                g1 += pr[(s * R + 1 * NU + q) * 64 + cb];
                g2 += pr[(s * R + 2 * NU + q) * 64 + cb];
                g3 += pr[(s * R + 3 * NU + q) * 64 + cb];
            }
            float iv = 1.0f / (1.0f + expf(-g0));
            float fv = 1.0f / (1.0f + expf(-g1));
            float gv = tanhf(g2);
            float ov = 1.0f / (1.0f + expf(-g3));
            float cn = fv * c_val + iv * gv;
            float hn = ov * tanhf(cn);
            c_val = fmaxf(cn, 0.0f);
            g_hr[(size_t)(t + 1) * (H1 * BATCH) + hr_off] = fmaxf(hn, 0.0f);
        }

        // ---- grid barrier ----
        __syncthreads();
        if (tid == 0) {
            __threadfence();
            atomicAdd(&g_bar, 1u);
            unsigned target = (unsigned)(t + 1) * GRID_R;
            unsigned v;
            do {
                asm volatile("ld.acquire.gpu.u32 %0, [%1];" : "=r"(v) : "l"(&g_bar));
            } while (v < target);
        }
        __syncthreads();
    }
}

__global__ void __launch_bounds__(256, 1) k_rec(const float* __restrict__ Whh) {
    __shared__ float ws[12 * H1];       // max R=12
    __shared__ float pr[4 * 12 * 64];
    const int bid = blockIdx.x;
    if (bid < 104) rec_body<3>(Whh, bid * 3, ws, pr);
    else           rec_body<2>(Whh, 312 + (bid - 104) * 2, ws, pr);
}

// =====================================================================
// Kernel 3: MLP head per timestep. grid 2048, block 256.
// =====================================================================
#define HS_F 25600
#define HEAD_SMEM_B ((HS_F + H2 * BATCH) * 4)

__global__ void __launch_bounds__(256) k_head(const float* __restrict__ Wfc,
                                              const float* __restrict__ bfc,
                                              const float* __restrict__ Wout,
                                              const float* __restrict__ bout,
                                              float* __restrict__ out) {
    extern __shared__ float sm[];
    float* hs  = sm;
    float* hid = sm + HS_F;
    const int t = blockIdx.x;
    const int tid = threadIdx.x;

    const float4* hsrc = (const float4*)(g_hr + (size_t)(t + 1) * (H1 * BATCH));
    for (int i = tid; i < (H1 * BATCH) / 4; i += 256)
        ((float4*)hs)[i] = hsrc[i];
    __syncthreads();

    const int jrow = tid >> 4;
    const int bq   = (tid & 15) * 4;
    for (int j = jrow; j < H2; j += 16) {
        float bv = bfc[j];
        float4 acc = make_float4(bv, bv, bv, bv);
        const float4* wr = (const float4*)(Wfc + (size_t)j * H1);
        #pragma unroll 4
        for (int k4 = 0; k4 < K4; k4++) {
            float4 w4 = wr[k4];
            float4 h0 = *(const float4*)&hs[k4 * 256 + (bq + 0) * 4];
            float4 h1 = *(const float4*)&hs[k4 * 256 + (bq + 1) * 4];
            float4 h2 = *(const float4*)&hs[k4 * 256 + (bq + 2) * 4];
            float4 h3 = *(const float4*)&hs[k4 * 256 + (bq + 3) * 4];
            acc.x += w4.x * h0.x + w4.y * h0.y + w4.z * h0.z + w4.w * h0.w;
            acc.y += w4.x * h1.x + w4.y * h1.y + w4.z * h1.z + w4.w * h1.w;
            acc.z += w4.x * h2.x + w4.y * h2.y + w4.z * h2.z + w4.w * h2.w;
            acc.w += w4.x * h3.x + w4.y * h3.y + w4.z * h3.z + w4.w * h3.w;
        }
        acc.x = fmaxf(acc.x, 0.f); acc.y = fmaxf(acc.y, 0.f);
        acc.z = fmaxf(acc.z, 0.f); acc.w = fmaxf(acc.w, 0.f);
        *(float4*)&hid[j * BATCH + bq] = acc;
    }
    __syncthreads();

    if (tid < BATCH) {
        float s = bout[0];
        #pragma unroll 8
        for (int j = 0; j < H2; j++)
            s += hid[j * BATCH + tid] * Wout[j];
        out[(size_t)t * BATCH + tid] = 1.0f / (1.0f + expf(-s));
    }
}

// =====================================================================
extern "C" void kernel_launch(void* const* d_in, const int* in_sizes, int n_in,
                              void* d_out, int out_size) {
    const float* word = (const float*)d_in[0];
    const float* Wih  = (const float*)d_in[1];
    const float* Whh  = (const float*)d_in[2];
    const float* bih  = (const float*)d_in[3];
    const float* bhh  = (const float*)d_in[4];
    const float* Wfc  = (const float*)d_in[5];
    const float* bfc  = (const float*)d_in[6];
    const float* Wout = (const float*)d_in[7];
    const float* bout = (const float*)d_in[8];
    float* out = (float*)d_out;

    cudaFuncSetAttribute(k_head, cudaFuncAttributeMaxDynamicSharedMemorySize, HEAD_SMEM_B);

    k_xw<<<dim3(25, T_STEPS), 256>>>(word, Wih, bih, bhh);
    k_rec<<<GRID_R, 256>>>(Whh);
    k_head<<<T_STEPS, 256, HEAD_SMEM_B>>>(Wfc, bfc, Wout, bout, out);
}